// round 16
// baseline (speedup 1.0000x reference)
#include <cuda_runtime.h>
#include <cuda_bf16.h>
#include <math.h>
#include <stdint.h>

// Flash attention (Q=K=V=feat^T), mma.sync m16n8k16 bf16, BM=64 / 8 warps /
// 256 threads, 2 CTAs per SM.  Main kernel = R11/R15 (measured best).
// R16: single fused pre-pass — transpose+convert x -> g_xbf with coalesced
// uint4 stores AND per-row |f|^2 in the same kernel (no rowsq launch, no
// 16MB re-read).  MUFU ex2 softmax, l via PV MMA vs all-ones B, V = K^T via
// ldmatrix.trans, exact fp32 diagonal correction on the t==bx tile.

#define NP 4096
#define CDIM 256
#define BM 64
#define BN 64
#define NTILES (NP / BN)
#define MAXB 8
#define KBUF 32768

// smem byte offsets (main kernel)
#define OFF_Q     0         // [64][256] bf16, 512B rows, swizzled (32KB)
#define OFF_K0    32768     // [64][256] bf16 x2 buffers (32KB each)
#define OFF_P     98304     // [64][64] bf16, 128B rows (8KB)
#define OFF_PDIAG 106496    // 64 f32
#define SMEM_TOTAL 106752   // x2 CTAs = 213.5KB

__device__ __nv_bfloat16 g_xbf[(size_t)MAXB * NP * CDIM];   // 16 MB
__device__ float g_mhat[MAXB * NP];

__device__ __forceinline__ uint32_t smem_u32(const void* p) {
    uint32_t a;
    asm("{ .reg .u64 t; cvta.to.shared.u64 t, %1; cvt.u32.u64 %0, t; }" : "=r"(a) : "l"(p));
    return a;
}

#define LDSM_X4(r0, r1, r2, r3, addr) \
    asm volatile("ldmatrix.sync.aligned.m8n8.x4.shared.b16 {%0,%1,%2,%3}, [%4];" \
        : "=r"(r0), "=r"(r1), "=r"(r2), "=r"(r3) : "r"(addr))
#define LDSM_X4T(r0, r1, r2, r3, addr) \
    asm volatile("ldmatrix.sync.aligned.m8n8.x4.trans.shared.b16 {%0,%1,%2,%3}, [%4];" \
        : "=r"(r0), "=r"(r1), "=r"(r2), "=r"(r3) : "r"(addr))

#define MMA_BF16(c, a0, a1, a2, a3, b0, b1) \
    asm volatile("mma.sync.aligned.m16n8k16.row.col.f32.bf16.bf16.f32 " \
        "{%0,%1,%2,%3}, {%4,%5,%6,%7}, {%8,%9}, {%0,%1,%2,%3};" \
        : "+f"((c)[0]), "+f"((c)[1]), "+f"((c)[2]), "+f"((c)[3]) \
        : "r"(a0), "r"(a1), "r"(a2), "r"(a3), "r"(b0), "r"(b1))

#define CP16(dst, src) \
    asm volatile("cp.async.cg.shared.global [%0], [%1], 16;" :: "r"(dst), "l"(src))
#define CP_COMMIT() asm volatile("cp.async.commit_group;" ::: "memory")
#define CP_WAIT0()  asm volatile("cp.async.wait_group 0;" ::: "memory")

__device__ __forceinline__ uint32_t pack_bf16x2(float lo, float hi) {
    uint32_t r;
    asm("cvt.rn.bf16x2.f32 %0, %1, %2;" : "=r"(r) : "f"(hi), "f"(lo));
    return r;
}
__device__ __forceinline__ float bf16lo(uint32_t v) { return __uint_as_float(v << 16); }
__device__ __forceinline__ float bf16hi(uint32_t v) { return __uint_as_float(v & 0xffff0000u); }

__device__ __forceinline__ uint32_t vp_off(int row, int j) {   // 128B rows (P)
    return (uint32_t)(row * 128 + ((((j >> 3) ^ (row & 7)) << 4) | ((j & 7) << 1)));
}

// hardware 2^y (MUFU pipe)
__device__ __forceinline__ float ex2f(float y) {
    float r;
    asm("ex2.approx.ftz.f32 %0, %1;" : "=f"(r) : "f"(y));
    return r;
}

// ---------- fused pre-pass: transpose+convert x -> g_xbf AND row |f|^2 ----------
// Block handles 32 j-rows x 256 c.  Load: warp reads 128B coalesced per (c).
// Store: each warp owns a j-row; lane packs 8 c into a uint4 -> 512B/warp
// fully coalesced.  Row sumsq reduced in-warp, no atomics, no second pass.
__global__ __launch_bounds__(256)
void prep_kernel(const float* __restrict__ x) {
    __shared__ float tile[32][257];      // [j][c], odd stride: conflict-free STS
    const int b  = blockIdx.y;
    const int j0 = blockIdx.x * 32;
    const int wid  = threadIdx.x >> 5;
    const int lane = threadIdx.x & 31;
    const float* xb = x + (size_t)b * CDIM * NP;

    // load: c = wid + 8k, j = lane (128B coalesced per row)
    #pragma unroll
    for (int k = 0; k < 32; k++) {
        int c = wid + k * 8;
        tile[lane][c] = xb[(size_t)c * NP + j0 + lane];
    }
    __syncthreads();

    // store: warp owns j rows {wid, wid+8, wid+16, wid+24}
    #pragma unroll
    for (int m = 0; m < 4; m++) {
        const int j = m * 8 + wid;
        const float* row = tile[j];
        float v[8];
        #pragma unroll
        for (int e = 0; e < 8; e++) v[e] = row[lane * 8 + e];
        float sq = 0.0f;
        #pragma unroll
        for (int e = 0; e < 8; e++) sq = fmaf(v[e], v[e], sq);
        uint4 pk;
        pk.x = pack_bf16x2(v[0], v[1]);
        pk.y = pack_bf16x2(v[2], v[3]);
        pk.z = pack_bf16x2(v[4], v[5]);
        pk.w = pack_bf16x2(v[6], v[7]);
        *reinterpret_cast<uint4*>(
            g_xbf + ((size_t)b * NP + j0 + j) * CDIM + lane * 8) = pk;
        #pragma unroll
        for (int off = 16; off >= 1; off >>= 1)
            sq += __shfl_xor_sync(0xffffffffu, sq, off);
        if (lane == 0) g_mhat[b * NP + j0 + j] = sq;
    }
}

// ---------------- main kernel (R11/R15, unchanged) ----------------
__global__ __launch_bounds__(256, 2)
void sap_mma_kernel(const float* __restrict__ x,
                    const float* __restrict__ thrp,
                    float* __restrict__ out) {
    extern __shared__ char smc[];
    const uint32_t sb = smem_u32(smc);
    const int tid  = threadIdx.x;
    const int wid  = tid >> 5;
    const int lane = tid & 31;
    const int b  = blockIdx.y;
    const int bx = blockIdx.x;
    const int i0 = bx * BM;

    const int wr  = wid & 3;     // S: rows 16*wr .. +16
    const int wc  = wid >> 2;    // S: cols 32*wc .. +32
    const int wr2 = wid & 1;     // PV: rows 32*wr2 .. +32
    const int wc2 = wid >> 1;    // PV: cols 64*wc2 .. +64

    float thr = 0.05f;
    if (thrp) {
        float tv = __ldg(thrp);
        if (tv > 1e-6f && tv < 1.0f) thr = tv;
    }
    const float thr16 = thr * 16.0f;
    const float K1 = 0.09016844005556021f;   // (1/16)*log2(e)

    const float* xb = x + (size_t)b * (CDIM * (size_t)NP);
    const __nv_bfloat16* xt = g_xbf + (size_t)b * NP * CDIM;
    float* pdiag = (float*)(smc + OFF_PDIAG);

    if (tid < 64) pdiag[tid] = 0.0f;

    // ---- prologue: cp.async Q tile + K tile 0 ----
    #pragma unroll
    for (int k = 0; k < 8; k++) {
        int q = tid + k * 256;
        int row = q >> 5, ch = q & 31;
        CP16(sb + OFF_Q + (uint32_t)(row * 512 + ((ch ^ (row & 7)) << 4)),
             xt + (size_t)(i0 + row) * CDIM + ch * 8);
    }
    #pragma unroll
    for (int k = 0; k < 8; k++) {
        int q = tid + k * 256;
        int row = q >> 5, ch = q & 31;
        CP16(sb + OFF_K0 + (uint32_t)(row * 512 + ((ch ^ (row & 7)) << 4)),
             xt + (size_t)row * CDIM + ch * 8);
    }
    CP_COMMIT();

    float mh2[2];
    #pragma unroll
    for (int h = 0; h < 2; h++)
        mh2[h] = __ldg(&g_mhat[b * NP + i0 + wr * 16 + h * 8 + (lane >> 2)]) * K1;

    float oacc[2][8][4];
    #pragma unroll
    for (int mt = 0; mt < 2; mt++)
        #pragma unroll
        for (int nt = 0; nt < 8; nt++)
            #pragma unroll
            for (int e = 0; e < 4; e++) oacc[mt][nt][e] = 0.0f;

    float lfr[2][4];
    #pragma unroll
    for (int mt = 0; mt < 2; mt++)
        #pragma unroll
        for (int e = 0; e < 4; e++) lfr[mt][e] = 0.0f;
    const uint32_t b_ones = 0x3F803F80u;     // bf16x2 (1.0, 1.0)

    const uint32_t sQ = sb + OFF_Q, sP = sb + OFF_P;

    CP_WAIT0();
    __syncthreads();

    #pragma unroll 1
    for (int t = 0; t < NTILES; t++) {
        const int j0 = t * BN;
        const uint32_t sK = sb + OFF_K0 + (uint32_t)((t & 1) * KBUF);
        const bool has_next = (t + 1 < NTILES);
        const __nv_bfloat16* ksrc = xt + (size_t)(j0 + BN) * CDIM;
        const uint32_t kdst = sb + OFF_K0 + (uint32_t)(((t + 1) & 1) * KBUF);

        // prefetch next K tile, first half (second half after the barrier)
        if (has_next) {
            #pragma unroll
            for (int k = 0; k < 4; k++) {
                int q = tid + k * 256;
                int row = q >> 5, ch = q & 31;
                CP16(kdst + (uint32_t)(row * 512 + ((ch ^ (row & 7)) << 4)),
                     ksrc + (size_t)row * CDIM + ch * 8);
            }
            CP_COMMIT();
        }

        // ---- S = Q K^T : warp rows [16wr,+16) x cols [32wc,+32) ----
        float sacc[4][4];
        #pragma unroll
        for (int nt = 0; nt < 4; nt++)
            #pragma unroll
            for (int e = 0; e < 4; e++) sacc[nt][e] = 0.0f;

        #pragma unroll
        for (int kk = 0; kk < 16; kk++) {
            uint32_t a[4], b0[4], b1[4];
            {
                int row = wr * 16 + (lane & 15);
                int ch = kk * 2 + (lane >> 4);
                LDSM_X4(a[0], a[1], a[2], a[3],
                        sQ + (uint32_t)(row * 512 + ((ch ^ (row & 7)) << 4)));
            }
            {
                int nrow = wc * 32 + ((lane >> 4) << 3) + (lane & 7);
                int chb = kk * 2 + ((lane >> 3) & 1);
                LDSM_X4(b0[0], b0[1], b0[2], b0[3],
                        sK + (uint32_t)(nrow * 512 + ((chb ^ (nrow & 7)) << 4)));
                int nrow2 = nrow + 16;
                LDSM_X4(b1[0], b1[1], b1[2], b1[3],
                        sK + (uint32_t)(nrow2 * 512 + ((chb ^ (nrow2 & 7)) << 4)));
            }
            MMA_BF16(sacc[0], a[0], a[1], a[2], a[3], b0[0], b0[1]);
            MMA_BF16(sacc[1], a[0], a[1], a[2], a[3], b0[2], b0[3]);
            MMA_BF16(sacc[2], a[0], a[1], a[2], a[3], b1[0], b1[1]);
            MMA_BF16(sacc[3], a[0], a[1], a[2], a[3], b1[2], b1[3]);
        }

        // ---- softmax (fixed shift) -> bf16 P; diag handled only on t==bx ----
        if (t == bx) {
            #pragma unroll
            for (int h = 0; h < 2; h++) {
                const int r = wr * 16 + h * 8 + (lane >> 2);
                const int ig = i0 + r;
                const float mh = mh2[h];
                #pragma unroll
                for (int nt = 0; nt < 4; nt++) {
                    float s0 = sacc[nt][2 * h];
                    float s1 = sacc[nt][2 * h + 1];
                    float p0 = (s0 >= thr16) ? ex2f(fmaf(s0, K1, -mh)) : 0.0f;
                    float p1 = (s1 >= thr16) ? ex2f(fmaf(s1, K1, -mh)) : 0.0f;
                    const int jl = wc * 32 + nt * 8 + (lane & 3) * 2;
                    const int jg = j0 + jl;
                    if (jg == ig)          { pdiag[r] = p0; p0 = 0.0f; }
                    else if (jg + 1 == ig) { pdiag[r] = p1; p1 = 0.0f; }
                    *(uint32_t*)(smc + OFF_P + vp_off(r, jl)) = pack_bf16x2(p0, p1);
                }
            }
        } else {
            #pragma unroll
            for (int h = 0; h < 2; h++) {
                const int r = wr * 16 + h * 8 + (lane >> 2);
                const float mh = mh2[h];
                #pragma unroll
                for (int nt = 0; nt < 4; nt++) {
                    float s0 = sacc[nt][2 * h];
                    float s1 = sacc[nt][2 * h + 1];
                    float p0 = (s0 >= thr16) ? ex2f(fmaf(s0, K1, -mh)) : 0.0f;
                    float p1 = (s1 >= thr16) ? ex2f(fmaf(s1, K1, -mh)) : 0.0f;
                    const int jl = wc * 32 + nt * 8 + (lane & 3) * 2;
                    *(uint32_t*)(smc + OFF_P + vp_off(r, jl)) = pack_bf16x2(p0, p1);
                }
            }
        }
        __syncthreads();   // P complete

        // prefetch next K tile, second half
        if (has_next) {
            #pragma unroll
            for (int k = 4; k < 8; k++) {
                int q = tid + k * 256;
                int row = q >> 5, ch = q & 31;
                CP16(kdst + (uint32_t)(row * 512 + ((ch ^ (row & 7)) << 4)),
                     ksrc + (size_t)row * CDIM + ch * 8);
            }
            CP_COMMIT();
        }

        // ---- O += P * K^T ; l += P * ones ----
        #pragma unroll
        for (int kk = 0; kk < 4; kk++) {
            uint32_t ap0[4], ap1[4];
            {
                int row = wr2 * 32 + (lane & 15);
                int ch = kk * 2 + (lane >> 4);
                LDSM_X4(ap0[0], ap0[1], ap0[2], ap0[3],
                        sP + (uint32_t)(row * 128 + ((ch ^ (row & 7)) << 4)));
            }
            {
                int row = wr2 * 32 + 16 + (lane & 15);
                int ch = kk * 2 + (lane >> 4);
                LDSM_X4(ap1[0], ap1[1], ap1[2], ap1[3],
                        sP + (uint32_t)(row * 128 + ((ch ^ (row & 7)) << 4)));
            }
            MMA_BF16(lfr[0], ap0[0], ap0[1], ap0[2], ap0[3], b_ones, b_ones);
            MMA_BF16(lfr[1], ap1[0], ap1[1], ap1[2], ap1[3], b_ones, b_ones);
            #pragma unroll
            for (int nt2 = 0; nt2 < 4; nt2++) {
                int jrow = kk * 16 + (lane & 15);
                int cch = wc2 * 8 + nt2 * 2 + (lane >> 4);
                uint32_t bv[4];
                LDSM_X4T(bv[0], bv[1], bv[2], bv[3],
                         sK + (uint32_t)(jrow * 512 + ((cch ^ (jrow & 7)) << 4)));
                MMA_BF16(oacc[0][nt2 * 2],     ap0[0], ap0[1], ap0[2], ap0[3], bv[0], bv[1]);
                MMA_BF16(oacc[0][nt2 * 2 + 1], ap0[0], ap0[1], ap0[2], ap0[3], bv[2], bv[3]);
                MMA_BF16(oacc[1][nt2 * 2],     ap1[0], ap1[1], ap1[2], ap1[3], bv[0], bv[1]);
                MMA_BF16(oacc[1][nt2 * 2 + 1], ap1[0], ap1[1], ap1[2], ap1[3], bv[2], bv[3]);
            }
        }

        CP_WAIT0();
        __syncthreads();   // next K tile resident; PV reads of P/K done
    }

    // ---------------- epilogue ----------------
    float* ob = out + (size_t)b * (CDIM * (size_t)NP) + i0;
    #pragma unroll
    for (int mt = 0; mt < 2; mt++) {
        const int r0 = wr2 * 32 + mt * 16 + (lane >> 2);
        const float pd0 = pdiag[r0], pd1 = pdiag[r0 + 8];
        const float inv0 = 1.0f / (lfr[mt][0] + pd0);
        const float inv1 = 1.0f / (lfr[mt][2] + pd1);
        #pragma unroll
        for (int nt = 0; nt < 8; nt++) {
            const int c = wc2 * 64 + nt * 8 + (lane & 3) * 2;
            const float x00 = __ldg(xb + (size_t)c * NP + i0 + r0);
            const float x10 = __ldg(xb + (size_t)(c + 1) * NP + i0 + r0);
            const float x01 = __ldg(xb + (size_t)c * NP + i0 + r0 + 8);
            const float x11 = __ldg(xb + (size_t)(c + 1) * NP + i0 + r0 + 8);
            ob[(size_t)c * NP + r0]           = fmaf(pd0, x00, oacc[mt][nt][0]) * inv0;
            ob[(size_t)(c + 1) * NP + r0]     = fmaf(pd0, x10, oacc[mt][nt][1]) * inv0;
            ob[(size_t)c * NP + r0 + 8]       = fmaf(pd1, x01, oacc[mt][nt][2]) * inv1;
            ob[(size_t)(c + 1) * NP + r0 + 8] = fmaf(pd1, x11, oacc[mt][nt][3]) * inv1;
        }
    }
}

extern "C" void kernel_launch(void* const* d_in, const int* in_sizes, int n_in,
                              void* d_out, int out_size) {
    const float* x = (const float*)d_in[0];
    const float* thrp = (n_in > 1) ? (const float*)d_in[1] : nullptr;
    float* out = (float*)d_out;

    int B = in_sizes[0] / (CDIM * NP);
    if (B < 1) B = 1;
    if (B > MAXB) B = MAXB;

    dim3 pg(NP / 32, B);
    prep_kernel<<<pg, 256>>>(x);

    cudaFuncSetAttribute(sap_mma_kernel,
                         cudaFuncAttributeMaxDynamicSharedMemorySize, SMEM_TOTAL);
    dim3 grid(NP / BM, B);
    sap_mma_kernel<<<grid, 256, SMEM_TOTAL>>>(x, thrp, out);
}

// round 17
// speedup vs baseline: 1.0048x; 1.0048x over previous
#include <cuda_runtime.h>
#include <cuda_bf16.h>
#include <math.h>
#include <stdint.h>

// FINAL: Flash attention (Q=K=V=feat^T), mma.sync m16n8k16 bf16, BM=64 /
// 8 warps / 256 threads, 2 CTAs per SM (best-measured configuration, R11).
// - S: single bf16 pass (softmax ratio cancels common-mode rounding)
// - PV: single bf16 pass, V = K^T via ldmatrix.trans (no V tile at all)
// - l: computed by the PV tensor core vs an all-ones B fragment (same rounded
//   P as the PV MMA -> numerator/denominator cancellation preserved)
// - softmax: MUFU ex2 with fixed per-row shift mhat = |f_i|^2 (diagonal
//   dominance; no row max, no online rescaling)
// - exact fp32 diagonal correction applied in the epilogue (diag extracted
//   only on the t==bx tile)
// - K double-buffered via 16B cp.async; pre-pass builds a transposed bf16
//   copy of x ([N][C], 512B rows matching the smem layout) + row norms.

#define NP 4096
#define CDIM 256
#define BM 64
#define BN 64
#define NTILES (NP / BN)
#define MAXB 8
#define KBUF 32768

// smem byte offsets
#define OFF_Q     0         // [64][256] bf16, 512B rows, swizzled (32KB)
#define OFF_K0    32768     // [64][256] bf16 x2 buffers (32KB each)
#define OFF_P     98304     // [64][64] bf16, 128B rows (8KB)
#define OFF_PDIAG 106496    // 64 f32
#define SMEM_TOTAL 106752   // x2 CTAs = 213.5KB

__device__ __nv_bfloat16 g_xbf[(size_t)MAXB * NP * CDIM];   // 16 MB
__device__ float g_mhat[MAXB * NP];

__device__ __forceinline__ uint32_t smem_u32(const void* p) {
    uint32_t a;
    asm("{ .reg .u64 t; cvta.to.shared.u64 t, %1; cvt.u32.u64 %0, t; }" : "=r"(a) : "l"(p));
    return a;
}

#define LDSM_X4(r0, r1, r2, r3, addr) \
    asm volatile("ldmatrix.sync.aligned.m8n8.x4.shared.b16 {%0,%1,%2,%3}, [%4];" \
        : "=r"(r0), "=r"(r1), "=r"(r2), "=r"(r3) : "r"(addr))
#define LDSM_X4T(r0, r1, r2, r3, addr) \
    asm volatile("ldmatrix.sync.aligned.m8n8.x4.trans.shared.b16 {%0,%1,%2,%3}, [%4];" \
        : "=r"(r0), "=r"(r1), "=r"(r2), "=r"(r3) : "r"(addr))

#define MMA_BF16(c, a0, a1, a2, a3, b0, b1) \
    asm volatile("mma.sync.aligned.m16n8k16.row.col.f32.bf16.bf16.f32 " \
        "{%0,%1,%2,%3}, {%4,%5,%6,%7}, {%8,%9}, {%0,%1,%2,%3};" \
        : "+f"((c)[0]), "+f"((c)[1]), "+f"((c)[2]), "+f"((c)[3]) \
        : "r"(a0), "r"(a1), "r"(a2), "r"(a3), "r"(b0), "r"(b1))

#define CP16(dst, src) \
    asm volatile("cp.async.cg.shared.global [%0], [%1], 16;" :: "r"(dst), "l"(src))
#define CP_COMMIT() asm volatile("cp.async.commit_group;" ::: "memory")
#define CP_WAIT0()  asm volatile("cp.async.wait_group 0;" ::: "memory")

__device__ __forceinline__ uint32_t pack_bf16x2(float lo, float hi) {
    uint32_t r;
    asm("cvt.rn.bf16x2.f32 %0, %1, %2;" : "=r"(r) : "f"(hi), "f"(lo));
    return r;
}
__device__ __forceinline__ float bf16lo(uint32_t v) { return __uint_as_float(v << 16); }
__device__ __forceinline__ float bf16hi(uint32_t v) { return __uint_as_float(v & 0xffff0000u); }

__device__ __forceinline__ uint32_t vp_off(int row, int j) {   // 128B rows (P)
    return (uint32_t)(row * 128 + ((((j >> 3) ^ (row & 7)) << 4) | ((j & 7) << 1)));
}

// hardware 2^y (MUFU pipe)
__device__ __forceinline__ float ex2f(float y) {
    float r;
    asm("ex2.approx.ftz.f32 %0, %1;" : "=f"(r) : "f"(y));
    return r;
}

// ---------------- pre-pass 1: transpose + convert x -> g_xbf ----------------
__global__ __launch_bounds__(256)
void transpose_conv_kernel(const float* __restrict__ x) {
    __shared__ float tile[32][33];
    const int b = blockIdx.z;
    const int j0 = blockIdx.x * 32;
    const int c0 = blockIdx.y * 32;
    const int tx = threadIdx.x & 31;
    const int ty = threadIdx.x >> 5;
    const float* xb = x + (size_t)b * CDIM * NP;
    #pragma unroll
    for (int k = 0; k < 4; k++)
        tile[ty + 8 * k][tx] = xb[(size_t)(c0 + ty + 8 * k) * NP + j0 + tx];
    __syncthreads();
    __nv_bfloat16* dst = g_xbf + ((size_t)b * NP + j0) * CDIM + c0;
    #pragma unroll
    for (int k = 0; k < 4; k++)
        dst[(size_t)(ty + 8 * k) * CDIM + tx] = __float2bfloat16(tile[tx][ty + 8 * k]);
}

// ---------------- pre-pass 2: g_mhat[b][j] = sum_c xbf^2 ----------------
__global__ __launch_bounds__(256)
void rowsq_kernel(int dummy) {
    const int b = blockIdx.y;
    const int wid = threadIdx.x >> 5, lane = threadIdx.x & 31;
    const int j = blockIdx.x * 8 + wid;
    const uint32_t* row = (const uint32_t*)(g_xbf + ((size_t)b * NP + j) * CDIM);
    float s = 0.0f;
    #pragma unroll
    for (int k = 0; k < 4; k++) {
        uint32_t u = row[lane + 32 * k];
        float a = bf16lo(u), c = bf16hi(u);
        s = fmaf(a, a, fmaf(c, c, s));
    }
    #pragma unroll
    for (int off = 16; off >= 1; off >>= 1)
        s += __shfl_xor_sync(0xffffffffu, s, off);
    if (lane == 0) g_mhat[b * NP + j] = s;
}

// ---------------- main kernel ----------------
__global__ __launch_bounds__(256, 2)
void sap_mma_kernel(const float* __restrict__ x,
                    const float* __restrict__ thrp,
                    float* __restrict__ out) {
    extern __shared__ char smc[];
    const uint32_t sb = smem_u32(smc);
    const int tid  = threadIdx.x;
    const int wid  = tid >> 5;
    const int lane = tid & 31;
    const int b  = blockIdx.y;
    const int bx = blockIdx.x;
    const int i0 = bx * BM;

    const int wr  = wid & 3;     // S: rows 16*wr .. +16
    const int wc  = wid >> 2;    // S: cols 32*wc .. +32
    const int wr2 = wid & 1;     // PV: rows 32*wr2 .. +32
    const int wc2 = wid >> 1;    // PV: cols 64*wc2 .. +64

    float thr = 0.05f;
    if (thrp) {
        float tv = __ldg(thrp);
        if (tv > 1e-6f && tv < 1.0f) thr = tv;
    }
    const float thr16 = thr * 16.0f;
    const float K1 = 0.09016844005556021f;   // (1/16)*log2(e)

    const float* xb = x + (size_t)b * (CDIM * (size_t)NP);
    const __nv_bfloat16* xt = g_xbf + (size_t)b * NP * CDIM;
    float* pdiag = (float*)(smc + OFF_PDIAG);

    if (tid < 64) pdiag[tid] = 0.0f;

    // ---- prologue: cp.async Q tile + K tile 0 ----
    #pragma unroll
    for (int k = 0; k < 8; k++) {
        int q = tid + k * 256;
        int row = q >> 5, ch = q & 31;
        CP16(sb + OFF_Q + (uint32_t)(row * 512 + ((ch ^ (row & 7)) << 4)),
             xt + (size_t)(i0 + row) * CDIM + ch * 8);
    }
    #pragma unroll
    for (int k = 0; k < 8; k++) {
        int q = tid + k * 256;
        int row = q >> 5, ch = q & 31;
        CP16(sb + OFF_K0 + (uint32_t)(row * 512 + ((ch ^ (row & 7)) << 4)),
             xt + (size_t)row * CDIM + ch * 8);
    }
    CP_COMMIT();

    float mh2[2];
    #pragma unroll
    for (int h = 0; h < 2; h++)
        mh2[h] = __ldg(&g_mhat[b * NP + i0 + wr * 16 + h * 8 + (lane >> 2)]) * K1;

    float oacc[2][8][4];
    #pragma unroll
    for (int mt = 0; mt < 2; mt++)
        #pragma unroll
        for (int nt = 0; nt < 8; nt++)
            #pragma unroll
            for (int e = 0; e < 4; e++) oacc[mt][nt][e] = 0.0f;

    // l accumulators as MMA C-frags (P @ ones); rows match oacc[mt] rows
    float lfr[2][4];
    #pragma unroll
    for (int mt = 0; mt < 2; mt++)
        #pragma unroll
        for (int e = 0; e < 4; e++) lfr[mt][e] = 0.0f;
    const uint32_t b_ones = 0x3F803F80u;     // bf16x2 (1.0, 1.0)

    const uint32_t sQ = sb + OFF_Q, sP = sb + OFF_P;

    CP_WAIT0();
    __syncthreads();

    #pragma unroll 1
    for (int t = 0; t < NTILES; t++) {
        const int j0 = t * BN;
        const uint32_t sK = sb + OFF_K0 + (uint32_t)((t & 1) * KBUF);
        const bool has_next = (t + 1 < NTILES);

        // prefetch next K tile into the other buffer
        if (has_next) {
            const __nv_bfloat16* ksrc = xt + (size_t)(j0 + BN) * CDIM;
            const uint32_t kdst = sb + OFF_K0 + (uint32_t)(((t + 1) & 1) * KBUF);
            #pragma unroll
            for (int k = 0; k < 8; k++) {
                int q = tid + k * 256;
                int row = q >> 5, ch = q & 31;
                CP16(kdst + (uint32_t)(row * 512 + ((ch ^ (row & 7)) << 4)),
                     ksrc + (size_t)row * CDIM + ch * 8);
            }
            CP_COMMIT();
        }

        // ---- S = Q K^T : warp rows [16wr,+16) x cols [32wc,+32) ----
        float sacc[4][4];
        #pragma unroll
        for (int nt = 0; nt < 4; nt++)
            #pragma unroll
            for (int e = 0; e < 4; e++) sacc[nt][e] = 0.0f;

        #pragma unroll
        for (int kk = 0; kk < 16; kk++) {
            uint32_t a[4], b0[4], b1[4];
            {
                int row = wr * 16 + (lane & 15);
                int ch = kk * 2 + (lane >> 4);
                LDSM_X4(a[0], a[1], a[2], a[3],
                        sQ + (uint32_t)(row * 512 + ((ch ^ (row & 7)) << 4)));
            }
            {
                int nrow = wc * 32 + ((lane >> 4) << 3) + (lane & 7);
                int chb = kk * 2 + ((lane >> 3) & 1);
                LDSM_X4(b0[0], b0[1], b0[2], b0[3],
                        sK + (uint32_t)(nrow * 512 + ((chb ^ (nrow & 7)) << 4)));
                int nrow2 = nrow + 16;
                LDSM_X4(b1[0], b1[1], b1[2], b1[3],
                        sK + (uint32_t)(nrow2 * 512 + ((chb ^ (nrow2 & 7)) << 4)));
            }
            MMA_BF16(sacc[0], a[0], a[1], a[2], a[3], b0[0], b0[1]);
            MMA_BF16(sacc[1], a[0], a[1], a[2], a[3], b0[2], b0[3]);
            MMA_BF16(sacc[2], a[0], a[1], a[2], a[3], b1[0], b1[1]);
            MMA_BF16(sacc[3], a[0], a[1], a[2], a[3], b1[2], b1[3]);
        }

        // ---- softmax (fixed shift) -> bf16 P; diag handled only on t==bx ----
        if (t == bx) {
            #pragma unroll
            for (int h = 0; h < 2; h++) {
                const int r = wr * 16 + h * 8 + (lane >> 2);
                const int ig = i0 + r;
                const float mh = mh2[h];
                #pragma unroll
                for (int nt = 0; nt < 4; nt++) {
                    float s0 = sacc[nt][2 * h];
                    float s1 = sacc[nt][2 * h + 1];
                    float p0 = (s0 >= thr16) ? ex2f(fmaf(s0, K1, -mh)) : 0.0f;
                    float p1 = (s1 >= thr16) ? ex2f(fmaf(s1, K1, -mh)) : 0.0f;
                    const int jl = wc * 32 + nt * 8 + (lane & 3) * 2;
                    const int jg = j0 + jl;
                    if (jg == ig)          { pdiag[r] = p0; p0 = 0.0f; }
                    else if (jg + 1 == ig) { pdiag[r] = p1; p1 = 0.0f; }
                    *(uint32_t*)(smc + OFF_P + vp_off(r, jl)) = pack_bf16x2(p0, p1);
                }
            }
        } else {
            #pragma unroll
            for (int h = 0; h < 2; h++) {
                const int r = wr * 16 + h * 8 + (lane >> 2);
                const float mh = mh2[h];
                #pragma unroll
                for (int nt = 0; nt < 4; nt++) {
                    float s0 = sacc[nt][2 * h];
                    float s1 = sacc[nt][2 * h + 1];
                    float p0 = (s0 >= thr16) ? ex2f(fmaf(s0, K1, -mh)) : 0.0f;
                    float p1 = (s1 >= thr16) ? ex2f(fmaf(s1, K1, -mh)) : 0.0f;
                    const int jl = wc * 32 + nt * 8 + (lane & 3) * 2;
                    *(uint32_t*)(smc + OFF_P + vp_off(r, jl)) = pack_bf16x2(p0, p1);
                }
            }
        }
        __syncthreads();   // P complete

        // ---- O += P * K^T ; l += P * ones (same rounded P -> cancellation) ----
        #pragma unroll
        for (int kk = 0; kk < 4; kk++) {
            uint32_t ap0[4], ap1[4];
            {
                int row = wr2 * 32 + (lane & 15);
                int ch = kk * 2 + (lane >> 4);
                LDSM_X4(ap0[0], ap0[1], ap0[2], ap0[3],
                        sP + (uint32_t)(row * 128 + ((ch ^ (row & 7)) << 4)));
            }
            {
                int row = wr2 * 32 + 16 + (lane & 15);
                int ch = kk * 2 + (lane >> 4);
                LDSM_X4(ap1[0], ap1[1], ap1[2], ap1[3],
                        sP + (uint32_t)(row * 128 + ((ch ^ (row & 7)) << 4)));
            }
            MMA_BF16(lfr[0], ap0[0], ap0[1], ap0[2], ap0[3], b_ones, b_ones);
            MMA_BF16(lfr[1], ap1[0], ap1[1], ap1[2], ap1[3], b_ones, b_ones);
            #pragma unroll
            for (int nt2 = 0; nt2 < 4; nt2++) {
                int jrow = kk * 16 + (lane & 15);
                int cch = wc2 * 8 + nt2 * 2 + (lane >> 4);
                uint32_t bv[4];
                LDSM_X4T(bv[0], bv[1], bv[2], bv[3],
                         sK + (uint32_t)(jrow * 512 + ((cch ^ (jrow & 7)) << 4)));
                MMA_BF16(oacc[0][nt2 * 2],     ap0[0], ap0[1], ap0[2], ap0[3], bv[0], bv[1]);
                MMA_BF16(oacc[0][nt2 * 2 + 1], ap0[0], ap0[1], ap0[2], ap0[3], bv[2], bv[3]);
                MMA_BF16(oacc[1][nt2 * 2],     ap1[0], ap1[1], ap1[2], ap1[3], bv[0], bv[1]);
                MMA_BF16(oacc[1][nt2 * 2 + 1], ap1[0], ap1[1], ap1[2], ap1[3], bv[2], bv[3]);
            }
        }

        CP_WAIT0();
        __syncthreads();   // next K tile resident; PV reads of P/K done
    }

    // ---------------- epilogue ----------------
    float* ob = out + (size_t)b * (CDIM * (size_t)NP) + i0;
    #pragma unroll
    for (int mt = 0; mt < 2; mt++) {
        const int r0 = wr2 * 32 + mt * 16 + (lane >> 2);
        const float pd0 = pdiag[r0], pd1 = pdiag[r0 + 8];
        const float inv0 = 1.0f / (lfr[mt][0] + pd0);
        const float inv1 = 1.0f / (lfr[mt][2] + pd1);
        #pragma unroll
        for (int nt = 0; nt < 8; nt++) {
            const int c = wc2 * 64 + nt * 8 + (lane & 3) * 2;
            const float x00 = __ldg(xb + (size_t)c * NP + i0 + r0);
            const float x10 = __ldg(xb + (size_t)(c + 1) * NP + i0 + r0);
            const float x01 = __ldg(xb + (size_t)c * NP + i0 + r0 + 8);
            const float x11 = __ldg(xb + (size_t)(c + 1) * NP + i0 + r0 + 8);
            ob[(size_t)c * NP + r0]           = fmaf(pd0, x00, oacc[mt][nt][0]) * inv0;
            ob[(size_t)(c + 1) * NP + r0]     = fmaf(pd0, x10, oacc[mt][nt][1]) * inv0;
            ob[(size_t)c * NP + r0 + 8]       = fmaf(pd1, x01, oacc[mt][nt][2]) * inv1;
            ob[(size_t)(c + 1) * NP + r0 + 8] = fmaf(pd1, x11, oacc[mt][nt][3]) * inv1;
        }
    }
}

extern "C" void kernel_launch(void* const* d_in, const int* in_sizes, int n_in,
                              void* d_out, int out_size) {
    const float* x = (const float*)d_in[0];
    const float* thrp = (n_in > 1) ? (const float*)d_in[1] : nullptr;
    float* out = (float*)d_out;

    int B = in_sizes[0] / (CDIM * NP);
    if (B < 1) B = 1;
    if (B > MAXB) B = MAXB;

    dim3 tg(NP / 32, CDIM / 32, B);
    transpose_conv_kernel<<<tg, 256>>>(x);
    dim3 rg(NP / 8, B);
    rowsq_kernel<<<rg, 256>>>(0);

    cudaFuncSetAttribute(sap_mma_kernel,
                         cudaFuncAttributeMaxDynamicSharedMemorySize, SMEM_TOTAL);
    dim3 grid(NP / BM, B);
    sap_mma_kernel<<<grid, 256, SMEM_TOTAL>>>(x, thrp, out);
}